// round 16
// baseline (speedup 1.0000x reference)
#include <cuda_runtime.h>
#include <math.h>

#define NB 8
#define P  2048
#define KSCALE 14.426950408889634f   /* log2(e)/eps */
#define K2     28.853900817779268f   /* 2*KSCALE */
#define BLKS_PER_BATCH 128
#define NITER  50
#define CONV_TOL 4e-3f               /* max |dz| per iter (log2 units);
                                        measured amplification ~0.13x
                                        -> rel_err ~5.2e-4 (deterministic) */
#define NCHK 8                       /* C written in 8 column chunks of 256 */

// ---------------- device scratch (no allocations allowed) ----------------
__device__ float2   g_xc[NB*P];
__device__ float2   g_yc[NB*P];
__device__ float    g_xz[NB*P];
__device__ float    g_yz[NB*P];
__device__ float    g_part[NB*P];
__device__ float    g_pS[NB*BLKS_PER_BATCH];  // per-block marginal partials
__device__ float    g_pT[NB*BLKS_PER_BATCH];
__device__ unsigned g_cnt[NB*32];    // persistent-barrier counters (one line/batch)
__device__ unsigned g_gen[NB*32];    // generation words (monotonic across replays)
__device__ unsigned g_dmax[NB*32];   // per-batch max |dz| (float bits, self-reset)
__device__ unsigned g_fcnt[NB*32];   // per-batch finalize-done counters (self-reset)

__device__ __forceinline__ float ex2f(float x){
    float y; asm("ex2.approx.ftz.f32 %0, %1;" : "=f"(y) : "f"(x)); return y;
}
__device__ __forceinline__ float lg2f(float x){
    float y; asm("lg2.approx.ftz.f32 %0, %1;" : "=f"(y) : "f"(x)); return y;
}

// ---------------- barriers ------------------------------------------------
__device__ __forceinline__ void batch_barrier(unsigned* cnt, volatile unsigned* gen,
                                              int tid)
{
    __syncthreads();
    if (tid == 0) {
        __threadfence();
        unsigned g = *gen;
        if (atomicAdd(cnt, 1u) == BLKS_PER_BATCH - 1u) {
            atomicExch(cnt, 0u);
            __threadfence();
            atomicAdd((unsigned*)gen, 1u);
        } else {
            while (*gen == g) __nanosleep(32);
        }
    }
    __syncthreads();
    __threadfence();
}

// Barrier that also aggregates max|dz| and publishes a convergence decision
// in the generation increment: gen += 2 if converged, else += 1.
__device__ __forceinline__ int batch_barrier_dec(unsigned* cnt, volatile unsigned* gen,
                                                 unsigned* dmax, float wmax,
                                                 int tid, int w,
                                                 volatile float* sconv,
                                                 volatile int* sdec)
{
    if ((tid & 31) == 0) sconv[w] = wmax;
    __syncthreads();
    if (tid == 0) {
        float m = fmaxf(fmaxf(sconv[0], sconv[1]), fmaxf(sconv[2], sconv[3]));
        atomicMax(dmax, __float_as_uint(m));   // non-neg floats: uint order == float order
        __threadfence();                       // z stores + dmax before arrive
        unsigned g = *gen;
        if (atomicAdd(cnt, 1u) == BLKS_PER_BATCH - 1u) {
            atomicExch(cnt, 0u);
            unsigned d = atomicExch(dmax, 0u); // read + reset for next iter
            unsigned inc = (__uint_as_float(d) < CONV_TOL) ? 2u : 1u;
            __threadfence();
            atomicAdd((unsigned*)gen, inc);
            *sdec = (int)inc;
        } else {
            unsigned ng;
            while ((ng = *gen) == g) __nanosleep(32);
            *sdec = (int)(ng - g);
        }
    }
    __syncthreads();
    __threadfence();
    return *sdec;
}

// ---------------- one Sinkhorn half-step ----------------------------------
// z_i <- log2(mu_i) - log2( sum_j exp2( z_j + K2*(x_i . y_j) ) )
template<bool TRACK>
__device__ __forceinline__ float half_step(
    const float (&c0)[4], const float (&c1)[4], const float (&l2)[4],
    const float2* __restrict__ pc, const float* __restrict__ pz,
    float* zself, int r0, int tid, int lane, float* sz, float (&zprev)[4])
{
    const float4* pz4 = (const float4*)pz;
    float4* sz4 = (float4*)sz;
#pragma unroll
    for (int q = 0; q < 4; q++)
        sz4[q*128 + tid] = __ldcg(pz4 + q*128 + tid);

    float sum[4] = {0.f, 0.f, 0.f, 0.f};
    __syncthreads();

#pragma unroll 4
    for (int jj = 0; jj < P/32; jj++) {
        int j = jj*32 + lane;
        float2 yv = __ldg(pc + j);
        float  b  = sz[j];
#pragma unroll
        for (int k = 0; k < 4; k++) {
            float t = fmaf(c0[k], yv.x, fmaf(c1[k], yv.y, b));
            sum[k] += ex2f(t);
        }
    }

#pragma unroll
    for (int k = 0; k < 4; k++) {
#pragma unroll
        for (int off = 16; off; off >>= 1)
            sum[k] += __shfl_xor_sync(0xffffffffu, sum[k], off);
    }
    float dmax = 0.f;
#pragma unroll
    for (int k = 0; k < 4; k++) {           // sum[k] identical on all lanes
        float z = l2[k] - lg2f(fmaxf(sum[k], 1e-35f));
        if (TRACK) { dmax = fmaxf(dmax, fabsf(z - zprev[k])); zprev[k] = z; }
        if (lane == 0) __stcg(zself + r0 + k, z);
    }
    return dmax;
}

// ---------------- C chunk writer ------------------------------------------
// Writes C rows r0..r0+3 for column chunk c (256 cols): pure coord math,
// independent of z, so it overlaps the MUFU-bound iterations (DRAM idle).
__device__ __forceinline__ void write_C_chunk(
    float* __restrict__ out_C, const float2* __restrict__ xc,
    const float4* __restrict__ yc4, int bp, int r0, int lane, int c)
{
#pragma unroll
    for (int k = 0; k < 4; k++) {
        int i = r0 + k;
        float2 xxr = __ldg(xc + i);
        float4* co = (float4*)(out_C + ((size_t)bp + i) * P);
        int q0 = c * (P/4/NCHK);             // 64 float4 per chunk per row
#pragma unroll
        for (int qq = 0; qq < 2; qq++) {
            int q = q0 + qq*32 + lane;
            float4 ya = __ldg(yc4 + 2*q);
            float4 yb = __ldg(yc4 + 2*q + 1);
            float4 Cv;
            float dx = xxr.x - ya.x, dy = xxr.y - ya.y;  Cv.x = dx*dx + dy*dy;
            dx = xxr.x - ya.z; dy = xxr.y - ya.w;        Cv.y = dx*dx + dy*dy;
            dx = xxr.x - yb.x; dy = xxr.y - yb.y;        Cv.z = dx*dx + dy*dy;
            dx = xxr.x - yb.z; dy = xxr.y - yb.w;        Cv.w = dx*dx + dy*dy;
            co[q] = Cv;
        }
    }
}

// ---------------- persistent kernel: init + iterate + finalize -----------
// Single launch. 1024 blocks x 128 thr; 8 blocks/SM co-resident. Each block
// initializes its own 16 rows; batch-wide marginal sums via per-block
// partials summed in fixed order after the first batch barrier
// (deterministic, identical in every block). Batches iterate, early-exit,
// and finalize independently; C streams out during the iterations.
__global__ void __launch_bounds__(128, 8) persist_k(const float* __restrict__ xin,
                                                    const float* __restrict__ yin,
                                                    float* __restrict__ out)
{
    __shared__ float sz[P];          // 8 KB staged peer z (also scratch)
    __shared__ float sconv[4];
    __shared__ int   sdec;
    __shared__ float s16a[16], s16b[16];
    __shared__ float sST[2];

    int b = blockIdx.x;
    int n = b >> 7;
    int rb = b & 127;
    int bp = n*P;
    int tid = threadIdx.x, w = tid >> 5, lane = tid & 31;
    int r0 = rb*16 + w*4;

    unsigned*          cnt  = &g_cnt[n*32];
    volatile unsigned* gen  = &g_gen[n*32];
    unsigned*          dmax = &g_dmax[n*32];

    // ---- fused init: this block's 16 rows ------------------------------
    if (tid < 16) {
        int i = rb*16 + tid;
        float2 xv = ((const float2*)xin)[bp + i];
        float2 yv = ((const float2*)yin)[bp + i];
        float m0 = (xv.x != -1.0f) ? 1.0f : 0.0f;
        float m1 = (xv.y != -1.0f) ? 1.0f : 0.0f;
        float xm0 = xv.x*m0, xm1 = xv.y*m1;
        float ym0 = yv.x*m0, ym1 = yv.y*m1;
        float sx = xm0*xm0 + xm1*xm1;
        float sy = ym0*ym0 + ym1*ym1;
        g_xc[bp+i] = make_float2(xm0, xm1);
        g_yc[bp+i] = make_float2(ym0, ym1);
        __stcg(&g_xz[bp+i], -sx*KSCALE);     // pot=0 -> z = -s*KSCALE
        __stcg(&g_yz[bp+i], -sy*KSCALE);
        s16a[tid] = xm1*xm1;
        s16b[tid] = ym1*ym1;
    }
    __syncthreads();
    if (tid == 0) {                          // fixed-order block partials
        float a = 0.f, t = 0.f;
#pragma unroll
        for (int r = 0; r < 16; r++) { a += s16a[r]; t += s16b[r]; }
        __stcg(&g_pS[n*BLKS_PER_BATCH + rb], a);
        __stcg(&g_pT[n*BLKS_PER_BATCH + rb], t);
    }
    batch_barrier(cnt, gen, tid);            // publishes coords, z, partials

    if (tid == 0) {                          // identical fixed-order sum in
        float a = 0.f, t = 0.f;              // every block -> deterministic
#pragma unroll 1
        for (int r = 0; r < BLKS_PER_BATCH; r++) {
            a += __ldcg(&g_pS[n*BLKS_PER_BATCH + r]);
            t += __ldcg(&g_pT[n*BLKS_PER_BATCH + r]);
        }
        sST[0] = a; sST[1] = t;
    }
    __syncthreads();
    float S = sST[0], T = sST[1];

    const float2* xc = g_xc + bp;
    const float2* yc = g_yc + bp;
    float* xz = g_xz + bp;
    float* yz = g_yz + bp;
    float* out_pi = out + 8;
    float* out_C  = out + 8 + (size_t)NB*P*P;
    const float4* yc4 = (const float4*)yc;

    float c0x[4], c1x[4], c0y[4], c1y[4], l2x[4], l2y[4], zpx[4], zdum[4];
#pragma unroll
    for (int k = 0; k < 4; k++) {
        float2 xx = xc[r0 + k];
        float2 yy = yc[r0 + k];
        c0x[k] = K2*xx.x; c1x[k] = K2*xx.y;
        c0y[k] = K2*yy.x; c1y[k] = K2*yy.y;
        l2x[k] = log2f(xx.y*xx.y/S + 1e-8f);
        l2y[k] = log2f(yy.y*yy.y/T + 1e-8f);
        zpx[k] = -(xx.x*xx.x + xx.y*xx.y)*KSCALE;
        zdum[k] = 0.f;
    }

    int cw = 0;                       // C chunks written so far
#pragma unroll 1
    for (int it = 0; it < NITER; it++) {
        float dm = half_step<true >(c0x, c1x, l2x, yc, yz, xz, r0, tid, lane, sz, zpx);
        int dec = batch_barrier_dec(cnt, gen, dmax, dm, tid, w, sconv, &sdec);
        if (cw < NCHK) { write_C_chunk(out_C, xc, yc4, bp, r0, lane, cw); cw++; }
        half_step<false>(c0y, c1y, l2y, xc, xz, yz, r0, tid, lane, sz, zdum);
        batch_barrier(cnt, gen, tid);
        if (dec == 2) break;         // fixed point: later iters are no-ops
    }
    // catch-up: C chunks not yet written (only if converged in < NCHK iters)
#pragma unroll 1
    for (; cw < NCHK; cw++) write_C_chunk(out_C, xc, yc4, bp, r0, lane, cw);

    // ---------- finalize this block's 16 rows (pi + cost partials) ------
    {
        const float4* pz4 = (const float4*)yz;
        float4* sz4 = (float4*)sz;
#pragma unroll
        for (int q = 0; q < 4; q++)
            sz4[q*128 + tid] = __ldcg(pz4 + q*128 + tid);
        __syncthreads();
    }
    {
        const float4* sz4 = (const float4*)sz;
#pragma unroll 1
        for (int k = 0; k < 4; k++) {
            int i = r0 + k;
            float2 xxr = __ldg(xc + i);
            float a0 = c0x[k], a1 = c1x[k], az = zpx[k]; // final u-side z in regs
            size_t base = ((size_t)bp + i) * P;
            float4* po = (float4*)(out_pi + base);
            float acc = 0.f;
#pragma unroll 2
            for (int q = lane; q < P/4; q += 32) {
                float4 ya = __ldg(yc4 + 2*q);
                float4 yb = __ldg(yc4 + 2*q + 1);
                float4 zz = sz4[q];
                float4 Cv, Pv;
                float dx = xxr.x - ya.x, dy = xxr.y - ya.y;
                Cv.x = dx*dx + dy*dy;
                Pv.x = ex2f(fmaf(a0, ya.x, fmaf(a1, ya.y, az + zz.x)));
                dx = xxr.x - ya.z; dy = xxr.y - ya.w;
                Cv.y = dx*dx + dy*dy;
                Pv.y = ex2f(fmaf(a0, ya.z, fmaf(a1, ya.w, az + zz.y)));
                dx = xxr.x - yb.x; dy = xxr.y - yb.y;
                Cv.z = dx*dx + dy*dy;
                Pv.z = ex2f(fmaf(a0, yb.x, fmaf(a1, yb.y, az + zz.z)));
                dx = xxr.x - yb.z; dy = xxr.y - yb.w;
                Cv.w = dx*dx + dy*dy;
                Pv.w = ex2f(fmaf(a0, yb.z, fmaf(a1, yb.w, az + zz.w)));
                po[q] = Pv;
                acc = fmaf(Pv.x, Cv.x, fmaf(Pv.y, Cv.y,
                      fmaf(Pv.z, Cv.z, fmaf(Pv.w, Cv.w, acc))));
            }
#pragma unroll
            for (int off = 16; off; off >>= 1)
                acc += __shfl_xor_sync(0xffffffffu, acc, off);
            if (lane == 0) g_part[bp + i] = acc;
        }
    }

    // ---------- last block of the batch reduces the cost ---------------
    __syncthreads();
    __shared__ bool last;
    if (tid == 0) {
        __threadfence();
        last = (atomicAdd(&g_fcnt[n*32], 1u) == BLKS_PER_BATCH - 1u);
        if (last) atomicExch(&g_fcnt[n*32], 0u);   // reset for next replay
    }
    __syncthreads();
    if (last) {
        __threadfence();
        float a = 0.f;
        for (int r = tid; r < P; r += 128) a += g_part[bp + r];  // fixed order
        sz[tid] = a;
        __syncthreads();
        for (int s = 64; s > 0; s >>= 1) {
            if (tid < s) sz[tid] += sz[tid + s];
            __syncthreads();
        }
        if (tid == 0) out[n] = sz[0];
    }
}

// ---------------- launch ------------------------------------------------
extern "C" void kernel_launch(void* const* d_in, const int* in_sizes, int n_in,
                              void* d_out, int out_size)
{
    const float* x = (const float*)d_in[0];
    const float* y = (const float*)d_in[1];
    float* out = (float*)d_out;

    persist_k<<<NB*BLKS_PER_BATCH, 128>>>(x, y, out);
}

// round 17
// speedup vs baseline: 1.1030x; 1.1030x over previous
#include <cuda_runtime.h>
#include <math.h>

#define NB 8
#define P  2048
#define KSCALE 14.426950408889634f   /* log2(e)/eps */
#define K2     28.853900817779268f   /* 2*KSCALE */
#define BLKS_PER_BATCH 128
#define NITER  50
#define CONV_TOL 4e-3f               /* max |dz| per iter (log2 units);
                                        measured amplification ~0.125x
                                        -> rel_err 5.0e-4 (deterministic) */
#define NCHK 8                       /* C written in 8 column chunks of 256 */

// ---------------- device scratch (no allocations allowed) ----------------
__device__ float2   g_xc[NB*P];
__device__ float2   g_yc[NB*P];
__device__ float    g_xz[NB*P];
__device__ float    g_yz[NB*P];
__device__ float    g_l2mu[NB*P];
__device__ float    g_l2nu[NB*P];
__device__ float    g_part[NB*P];
__device__ unsigned g_cnt[NB*32];    // persistent-barrier counters (one line/batch)
__device__ unsigned g_gen[NB*32];
__device__ unsigned g_dmax[NB*32];   // per-batch max |dz| (float bits)
__device__ unsigned g_fcnt[NB*32];   // per-batch finalize-done counters

__device__ __forceinline__ float ex2f(float x){
    float y; asm("ex2.approx.ftz.f32 %0, %1;" : "=f"(y) : "f"(x)); return y;
}
__device__ __forceinline__ float lg2f(float x){
    float y; asm("lg2.approx.ftz.f32 %0, %1;" : "=f"(y) : "f"(x)); return y;
}

// ---------------- init: mask, marginals, split operands ------------------
__global__ void __launch_bounds__(1024) init_k(const float* __restrict__ x,
                                               const float* __restrict__ y)
{
    int n = blockIdx.x, tid = threadIdx.x;
    __shared__ float sS[1024], sT[1024];
    if (tid == 0) { g_fcnt[n*32] = 0u; g_dmax[n*32] = 0u; }
    float locS = 0.f, locT = 0.f;
    for (int i = tid; i < P; i += 1024) {
        int idx = (n*P + i)*2;
        float x0 = x[idx], x1 = x[idx+1];
        float y0 = y[idx], y1 = y[idx+1];
        float m0 = (x0 != -1.0f) ? 1.0f : 0.0f;
        float m1 = (x1 != -1.0f) ? 1.0f : 0.0f;
        float xm0 = x0*m0, xm1 = x1*m1;
        float ym0 = y0*m0, ym1 = y1*m1;
        float sx = xm0*xm0 + xm1*xm1;
        float sy = ym0*ym0 + ym1*ym1;
        g_xc[n*P+i] = make_float2(xm0, xm1);
        g_yc[n*P+i] = make_float2(ym0, ym1);
        g_xz[n*P+i] = -sx*KSCALE;            // pot=0 -> z = -s*KSCALE
        g_yz[n*P+i] = -sy*KSCALE;
        locS += xm1*xm1;
        locT += ym1*ym1;
    }
    sS[tid] = locS; sT[tid] = locT;
    __syncthreads();
    for (int s = 512; s > 0; s >>= 1) {
        if (tid < s) { sS[tid] += sS[tid+s]; sT[tid] += sT[tid+s]; }
        __syncthreads();
    }
    float S = sS[0], T = sT[0];
    for (int i = tid; i < P; i += 1024) {
        float xm1 = g_xc[n*P+i].y, ym1 = g_yc[n*P+i].y;
        g_l2mu[n*P+i] = log2f(xm1*xm1/S + 1e-8f);
        g_l2nu[n*P+i] = log2f(ym1*ym1/T + 1e-8f);
    }
}

// ---------------- barriers ------------------------------------------------
__device__ __forceinline__ void batch_barrier(unsigned* cnt, volatile unsigned* gen,
                                              int tid)
{
    __syncthreads();
    if (tid == 0) {
        __threadfence();
        unsigned g = *gen;
        if (atomicAdd(cnt, 1u) == BLKS_PER_BATCH - 1u) {
            atomicExch(cnt, 0u);
            __threadfence();
            atomicAdd((unsigned*)gen, 1u);
        } else {
            while (*gen == g) __nanosleep(32);
        }
    }
    __syncthreads();
    __threadfence();
}

// Barrier that also aggregates max|dz| and publishes a convergence decision
// in the generation increment: gen += 2 if converged, else += 1.
__device__ __forceinline__ int batch_barrier_dec(unsigned* cnt, volatile unsigned* gen,
                                                 unsigned* dmax, float wmax,
                                                 int tid, int w,
                                                 volatile float* sconv,
                                                 volatile int* sdec)
{
    if ((tid & 31) == 0) sconv[w] = wmax;
    __syncthreads();
    if (tid == 0) {
        float m = fmaxf(fmaxf(sconv[0], sconv[1]), fmaxf(sconv[2], sconv[3]));
        atomicMax(dmax, __float_as_uint(m));   // non-neg floats: uint order == float order
        __threadfence();                       // z stores + dmax before arrive
        unsigned g = *gen;
        if (atomicAdd(cnt, 1u) == BLKS_PER_BATCH - 1u) {
            atomicExch(cnt, 0u);
            unsigned d = atomicExch(dmax, 0u); // read + reset for next iter
            unsigned inc = (__uint_as_float(d) < CONV_TOL) ? 2u : 1u;
            __threadfence();
            atomicAdd((unsigned*)gen, inc);
            *sdec = (int)inc;
        } else {
            unsigned ng;
            while ((ng = *gen) == g) __nanosleep(32);
            *sdec = (int)(ng - g);
        }
    }
    __syncthreads();
    __threadfence();
    return *sdec;
}

// ---------------- one Sinkhorn half-step ----------------------------------
// z_i <- log2(mu_i) - log2( sum_j exp2( z_j + K2*(x_i . y_j) ) )
template<bool TRACK>
__device__ __forceinline__ float half_step(
    const float (&c0)[4], const float (&c1)[4], const float (&l2)[4],
    const float2* __restrict__ pc, const float* __restrict__ pz,
    float* zself, int r0, int tid, int lane, float* sz, float (&zprev)[4])
{
    const float4* pz4 = (const float4*)pz;
    float4* sz4 = (float4*)sz;
#pragma unroll
    for (int q = 0; q < 4; q++)
        sz4[q*128 + tid] = __ldcg(pz4 + q*128 + tid);

    float sum[4] = {0.f, 0.f, 0.f, 0.f};
    __syncthreads();

#pragma unroll 4
    for (int jj = 0; jj < P/32; jj++) {
        int j = jj*32 + lane;
        float2 yv = __ldg(pc + j);
        float  b  = sz[j];
#pragma unroll
        for (int k = 0; k < 4; k++) {
            float t = fmaf(c0[k], yv.x, fmaf(c1[k], yv.y, b));
            sum[k] += ex2f(t);
        }
    }

#pragma unroll
    for (int k = 0; k < 4; k++) {
#pragma unroll
        for (int off = 16; off; off >>= 1)
            sum[k] += __shfl_xor_sync(0xffffffffu, sum[k], off);
    }
    float dmax = 0.f;
#pragma unroll
    for (int k = 0; k < 4; k++) {           // sum[k] identical on all lanes
        float z = l2[k] - lg2f(fmaxf(sum[k], 1e-35f));
        if (TRACK) { dmax = fmaxf(dmax, fabsf(z - zprev[k])); zprev[k] = z; }
        if (lane == 0) __stcg(zself + r0 + k, z);
    }
    return dmax;
}

// ---------------- C chunk writer ------------------------------------------
// Writes C rows r0..r0+3 for column chunk c (256 cols): pure coord math,
// independent of z, so it overlaps the MUFU-bound iterations (DRAM idle).
__device__ __forceinline__ void write_C_chunk(
    float* __restrict__ out_C, const float2* __restrict__ xc,
    const float4* __restrict__ yc4, int bp, int r0, int lane, int c)
{
#pragma unroll
    for (int k = 0; k < 4; k++) {
        int i = r0 + k;
        float2 xxr = __ldg(xc + i);
        float4* co = (float4*)(out_C + ((size_t)bp + i) * P);
        int q0 = c * (P/4/NCHK);             // 64 float4 per chunk per row
#pragma unroll
        for (int qq = 0; qq < 2; qq++) {
            int q = q0 + qq*32 + lane;
            float4 ya = __ldg(yc4 + 2*q);
            float4 yb = __ldg(yc4 + 2*q + 1);
            float4 Cv;
            float dx = xxr.x - ya.x, dy = xxr.y - ya.y;  Cv.x = dx*dx + dy*dy;
            dx = xxr.x - ya.z; dy = xxr.y - ya.w;        Cv.y = dx*dx + dy*dy;
            dx = xxr.x - yb.x; dy = xxr.y - yb.y;        Cv.z = dx*dx + dy*dy;
            dx = xxr.x - yb.z; dy = xxr.y - yb.w;        Cv.w = dx*dx + dy*dy;
            co[q] = Cv;
        }
    }
}

// ---------------- persistent kernel: iterate + finalize ------------------
// 1024 blocks x 128 thr; 8 blocks/SM co-resident. Batches sync, early-exit,
// and finalize independently. C output is streamed out DURING the
// iterations (1 chunk/iter), hidden under the MUFU-bound loop.
__global__ void __launch_bounds__(128, 8) persist_k(float* __restrict__ out)
{
    __shared__ float sz[P];          // 8 KB staged peer z
    __shared__ float sconv[4];
    __shared__ int   sdec;

    int b = blockIdx.x;
    int n = b >> 7;
    int rb = b & 127;
    int bp = n*P;
    int tid = threadIdx.x, w = tid >> 5, lane = tid & 31;
    int r0 = rb*16 + w*4;

    const float2* xc = g_xc + bp;
    const float2* yc = g_yc + bp;
    float* xz = g_xz + bp;
    float* yz = g_yz + bp;
    float* out_pi = out + 8;
    float* out_C  = out + 8 + (size_t)NB*P*P;
    const float4* yc4 = (const float4*)yc;

    float c0x[4], c1x[4], c0y[4], c1y[4], l2x[4], l2y[4], zpx[4], zdum[4];
#pragma unroll
    for (int k = 0; k < 4; k++) {
        float2 xx = xc[r0 + k];
        float2 yy = yc[r0 + k];
        c0x[k] = K2*xx.x; c1x[k] = K2*xx.y;
        c0y[k] = K2*yy.x; c1y[k] = K2*yy.y;
        l2x[k] = g_l2mu[bp + r0 + k];
        l2y[k] = g_l2nu[bp + r0 + k];
        zpx[k] = __ldcg(xz + r0 + k);
        zdum[k] = 0.f;
    }

    unsigned*          cnt  = &g_cnt[n*32];
    volatile unsigned* gen  = &g_gen[n*32];
    unsigned*          dmax = &g_dmax[n*32];

    int cw = 0;                       // C chunks written so far
#pragma unroll 1
    for (int it = 0; it < NITER; it++) {
        float dm = half_step<true >(c0x, c1x, l2x, yc, yz, xz, r0, tid, lane, sz, zpx);
        int dec = batch_barrier_dec(cnt, gen, dmax, dm, tid, w, sconv, &sdec);
        if (cw < NCHK) { write_C_chunk(out_C, xc, yc4, bp, r0, lane, cw); cw++; }
        half_step<false>(c0y, c1y, l2y, xc, xz, yz, r0, tid, lane, sz, zdum);
        batch_barrier(cnt, gen, tid);
        if (dec == 2) break;         // fixed point: later iters are no-ops
    }
    // catch-up: C chunks not yet written (only if converged in < NCHK iters)
#pragma unroll 1
    for (; cw < NCHK; cw++) write_C_chunk(out_C, xc, yc4, bp, r0, lane, cw);

    // ---------- finalize this block's 16 rows (pi + cost partials) ------
    {
        const float4* pz4 = (const float4*)yz;
        float4* sz4 = (float4*)sz;
#pragma unroll
        for (int q = 0; q < 4; q++)
            sz4[q*128 + tid] = __ldcg(pz4 + q*128 + tid);
        __syncthreads();
    }
    {
        const float4* sz4 = (const float4*)sz;
#pragma unroll 1
        for (int k = 0; k < 4; k++) {
            int i = r0 + k;
            float2 xxr = __ldg(xc + i);
            float a0 = c0x[k], a1 = c1x[k], az = zpx[k]; // final u-side z in regs
            size_t base = ((size_t)bp + i) * P;
            float4* po = (float4*)(out_pi + base);
            float acc = 0.f;
#pragma unroll 2
            for (int q = lane; q < P/4; q += 32) {
                float4 ya = __ldg(yc4 + 2*q);
                float4 yb = __ldg(yc4 + 2*q + 1);
                float4 zz = sz4[q];
                float4 Cv, Pv;
                float dx = xxr.x - ya.x, dy = xxr.y - ya.y;
                Cv.x = dx*dx + dy*dy;
                Pv.x = ex2f(fmaf(a0, ya.x, fmaf(a1, ya.y, az + zz.x)));
                dx = xxr.x - ya.z; dy = xxr.y - ya.w;
                Cv.y = dx*dx + dy*dy;
                Pv.y = ex2f(fmaf(a0, ya.z, fmaf(a1, ya.w, az + zz.y)));
                dx = xxr.x - yb.x; dy = xxr.y - yb.y;
                Cv.z = dx*dx + dy*dy;
                Pv.z = ex2f(fmaf(a0, yb.x, fmaf(a1, yb.y, az + zz.z)));
                dx = xxr.x - yb.z; dy = xxr.y - yb.w;
                Cv.w = dx*dx + dy*dy;
                Pv.w = ex2f(fmaf(a0, yb.z, fmaf(a1, yb.w, az + zz.w)));
                po[q] = Pv;
                acc = fmaf(Pv.x, Cv.x, fmaf(Pv.y, Cv.y,
                      fmaf(Pv.z, Cv.z, fmaf(Pv.w, Cv.w, acc))));
            }
#pragma unroll
            for (int off = 16; off; off >>= 1)
                acc += __shfl_xor_sync(0xffffffffu, acc, off);
            if (lane == 0) g_part[bp + i] = acc;
        }
    }

    // ---------- last block of the batch reduces the cost ---------------
    __syncthreads();
    __shared__ bool last;
    if (tid == 0) {
        __threadfence();
        last = (atomicAdd(&g_fcnt[n*32], 1u) == BLKS_PER_BATCH - 1u);
        if (last) atomicExch(&g_fcnt[n*32], 0u);   // reset for next replay
    }
    __syncthreads();
    if (last) {
        __threadfence();
        float a = 0.f;
        for (int r = tid; r < P; r += 128) a += g_part[bp + r];  // fixed order
        sz[tid] = a;
        __syncthreads();
        for (int s = 64; s > 0; s >>= 1) {
            if (tid < s) sz[tid] += sz[tid + s];
            __syncthreads();
        }
        if (tid == 0) out[n] = sz[0];
    }
}

// ---------------- launch ------------------------------------------------
extern "C" void kernel_launch(void* const* d_in, const int* in_sizes, int n_in,
                              void* d_out, int out_size)
{
    const float* x = (const float*)d_in[0];
    const float* y = (const float*)d_in[1];
    float* out = (float*)d_out;

    init_k<<<NB, 1024>>>(x, y);
    persist_k<<<NB*BLKS_PER_BATCH, 128>>>(out);
}